// round 6
// baseline (speedup 1.0000x reference)
#include <cuda_runtime.h>

// KAN 3x3 convolution, fused closed-form cubic B-spline + silu, f32x2-packed.
// x: (32,256,256) f32 in [0,1); base_weight: (3,3); spline_weight: (3,3,8).
// out: (32,254,254) f32.
//
// For v in [0,1) the 8-basis cubic B-spline dot (uniform knots, h=0.4,
// lo=-2.2) reduces to a C^2 piecewise cubic with interior knots at 0.2, 0.6:
//   g_p(v) = c0 + c1 v + c2 v^2 + c3 v^3 + d1 (v-0.2)_+^3 + d2 (v-0.6)_+^3
//            + bw_p * silu(v)
// Only spline slots 2..7 are active for v in [0,1).
// Each thread evaluates 2 adjacent output columns; the pair is packed into
// one 64-bit register and the tap dot-products use fma.rn.f32x2 (FFMA2).
//
// R4 fix (unmeasured due to broker timeout, resubmitted verbatim): restore
// the r < HO retire guard. y0 can be 248, so retired rows reach 255 > 253;
// unguarded stores corrupted the next batch's rows 0-1 (measured 9.7e-2).

#define HH 256
#define WW 256
#define HO 254
#define WO 254
#define RPW 8            // output rows per warp
#define ITERS (RPW + 2)  // input rows walked per thread

typedef unsigned long long u64;

__device__ __forceinline__ u64 pk2(float lo, float hi) {
    u64 r; asm("mov.b64 %0, {%1, %2};" : "=l"(r) : "f"(lo), "f"(hi)); return r;
}
__device__ __forceinline__ u64 ffma2(u64 a, u64 b, u64 c) {
    u64 d; asm("fma.rn.f32x2 %0, %1, %2, %3;" : "=l"(d) : "l"(a), "l"(b), "l"(c)); return d;
}
__device__ __forceinline__ u64 fadd2(u64 a, u64 b) {
    u64 d; asm("add.rn.f32x2 %0, %1, %2;" : "=l"(d) : "l"(a), "l"(b)); return d;
}
__device__ __forceinline__ void unpk2(u64 a, float& lo, float& hi) {
    asm("mov.b64 {%0, %1}, %2;" : "=f"(lo), "=f"(hi) : "l"(a));
}

__global__ __launch_bounds__(128)
void kan_conv_kernel(const float* __restrict__ x,
                     const float* __restrict__ bwp,
                     const float* __restrict__ swp,
                     float* __restrict__ out) {
    const int lane = threadIdx.x;
    const int wrp  = threadIdx.y;
    const int c0   = blockIdx.x * 64 + lane * 2;          // output cols c0, c0+1
    const int y0   = (blockIdx.y * 4 + wrp) * RPW;        // first output row
    const int bat  = blockIdx.z;

    if (c0 >= WO) return;   // only lane 31 of strip 3 dies (c0 == 254)
    // Live threads have c0 <= 252, so input cols c0..c0+3 <= 255 all valid.
    // NOTE: y0 max is 248, so output rows reach y0+7 = 255 — rows 254,255 do
    // NOT exist (HO=254); the retire store must be guarded.

    const float* __restrict__ xb = x + (size_t)bat * (HH * WW);
    float* __restrict__ ob = out + (size_t)bat * (HO * WO);

    // ---------- derive transformed weights, packed (w,w) ----------
    u64 Wc1[9], Wc2[9], Wc3[9], Wd1[9], Wd2[9], Wbw[9];
    float cA0 = 0.f, cA1 = 0.f, cA2 = 0.f;  // summed constant terms per kernel row
    #pragma unroll
    for (int p = 0; p < 9; ++p) {
        const float S2 = __ldg(&swp[p * 8 + 2]);
        const float S3 = __ldg(&swp[p * 8 + 3]);
        const float S4 = __ldg(&swp[p * 8 + 4]);
        const float S5 = __ldg(&swp[p * 8 + 5]);
        const float S6 = __ldg(&swp[p * 8 + 6]);
        const float S7 = __ldg(&swp[p * 8 + 7]);
        const float i6 = 1.0f / 6.0f;
        // piece-0 cubic in local param t = 2.5 v + 0.5 (v in [0,0.2))
        const float a0 = (S2 + 4.f * S3 + S4) * i6;
        const float a1 = (S4 - S2) * 0.5f;
        const float a2 = (S2 - 2.f * S3 + S4) * 0.5f;
        const float a3  = (S5 - S2 + 3.f * (S3 - S4)) * i6;  // t^3 coef, piece 0
        const float a3b = (S6 - S3 + 3.f * (S4 - S5)) * i6;  // piece 1
        const float a3c = (S7 - S4 + 3.f * (S5 - S6)) * i6;  // piece 2
        // expand to polynomial in v (t = 2.5 v + 0.5)
        const float cc0 = a0 + 0.5f * a1 + 0.25f * a2 + 0.125f * a3;
        const float c1 = 2.5f    * (a1 + a2 + 0.75f * a3);
        const float c2 = 6.25f   * (a2 + 1.5f * a3);
        const float c3 = 15.625f * a3;
        const float d1 = 15.625f * (a3b - a3);   // jump at knot 0.2
        const float d2 = 15.625f * (a3c - a3b);  // jump at knot 0.6
        const float bw = __ldg(&bwp[p]);
        Wc1[p] = pk2(c1, c1); Wc2[p] = pk2(c2, c2); Wc3[p] = pk2(c3, c3);
        Wd1[p] = pk2(d1, d1); Wd2[p] = pk2(d2, d2); Wbw[p] = pk2(bw, bw);
        if (p < 3)      cA0 += cc0;
        else if (p < 6) cA1 += cc0;
        else            cA2 += cc0;
    }
    const u64 cA0p = pk2(cA0, cA0);
    const u64 cA1p = pk2(cA1, cA1);
    const u64 cA2p = pk2(cA2, cA2);

    // rolling accumulators: acc0 = oldest (retires this iter, tap row a=2),
    // acc1 = a=1, acc2 = newest (a=0). Packed (col c0, col c0+1).
    u64 acc0 = 0ull, acc1 = 0ull, acc2 = 0ull;

    #pragma unroll
    for (int it = 0; it < ITERS; ++it) {
        const int y = y0 + it;

        float fv[4] = {0.f, 0.f, 0.f, 0.f};
        if (y < HH) {
            const float2 p01 = *reinterpret_cast<const float2*>(xb + y * WW + c0);
            const float2 p23 = *reinterpret_cast<const float2*>(xb + y * WW + c0 + 2);
            fv[0] = p01.x; fv[1] = p01.y; fv[2] = p23.x; fv[3] = p23.y;
        }

        // scalar features for the 4 input columns
        float fv2[4], fv3[4], fR1[4], fR2[4], fs[4];
        #pragma unroll
        for (int j = 0; j < 4; ++j) {
            const float v = fv[j];
            const float q = v * v;
            fv2[j] = q;
            fv3[j] = q * v;
            const float r1 = fmaxf(v - 0.2f, 0.f);
            const float r2 = fmaxf(v - 0.6f, 0.f);
            fR1[j] = r1 * r1 * r1;
            fR2[j] = r2 * r2 * r2;
            fs[j]  = __fdividef(v, 1.f + __expf(-v));   // silu
        }

        // packed feature pairs: P*[b] = (feat[b], feat[b+1])
        u64 Pv[3], Pv2[3], Pv3[3], PR1[3], PR2[3], Ps[3];
        #pragma unroll
        for (int b = 0; b < 3; ++b) {
            Pv[b]  = pk2(fv[b],  fv[b + 1]);
            Pv2[b] = pk2(fv2[b], fv2[b + 1]);
            Pv3[b] = pk2(fv3[b], fv3[b + 1]);
            PR1[b] = pk2(fR1[b], fR1[b + 1]);
            PR2[b] = pk2(fR2[b], fR2[b + 1]);
            Ps[b]  = pk2(fs[b],  fs[b + 1]);
        }

        // per-row constant terms (each output receives each exactly once)
        u64 r2acc = fadd2(acc2, cA0p);   // tap row a=0 -> newest output row
        u64 r1acc = fadd2(acc1, cA1p);   // a=1
        u64 r0acc = fadd2(acc0, cA2p);   // a=2 -> retiring output row

        // 9 taps x 6 features, three independent FFMA2 chains (one per tap row)
        #pragma unroll
        for (int b = 0; b < 3; ++b) {
            const int p0 = b, p1 = 3 + b, p2 = 6 + b;
            r2acc = ffma2(Wc1[p0], Pv[b],  r2acc);
            r1acc = ffma2(Wc1[p1], Pv[b],  r1acc);
            r0acc = ffma2(Wc1[p2], Pv[b],  r0acc);
            r2acc = ffma2(Wc2[p0], Pv2[b], r2acc);
            r1acc = ffma2(Wc2[p1], Pv2[b], r1acc);
            r0acc = ffma2(Wc2[p2], Pv2[b], r0acc);
            r2acc = ffma2(Wc3[p0], Pv3[b], r2acc);
            r1acc = ffma2(Wc3[p1], Pv3[b], r1acc);
            r0acc = ffma2(Wc3[p2], Pv3[b], r0acc);
            r2acc = ffma2(Wd1[p0], PR1[b], r2acc);
            r1acc = ffma2(Wd1[p1], PR1[b], r1acc);
            r0acc = ffma2(Wd1[p2], PR1[b], r0acc);
            r2acc = ffma2(Wd2[p0], PR2[b], r2acc);
            r1acc = ffma2(Wd2[p1], PR2[b], r1acc);
            r0acc = ffma2(Wd2[p2], PR2[b], r0acc);
            r2acc = ffma2(Wbw[p0], Ps[b],  r2acc);
            r1acc = ffma2(Wbw[p1], Ps[b],  r1acc);
            r0acc = ffma2(Wbw[p2], Ps[b],  r0acc);
        }

        // retire the oldest accumulator (output row y0 + it - 2).
        // GUARD REQUIRED: for y0 == 248 the retired row reaches 255 >= HO.
        if (it >= 2) {
            const int r = y0 + it - 2;
            if (r < HO) {
                float lo, hi; unpk2(r0acc, lo, hi);
                *reinterpret_cast<float2*>(ob + r * WO + c0) = make_float2(lo, hi);
            }
        }
        acc0 = r1acc;
        acc1 = r2acc;
        acc2 = 0ull;
    }
}

extern "C" void kernel_launch(void* const* d_in, const int* in_sizes, int n_in,
                              void* d_out, int out_size) {
    const float* x  = (const float*)d_in[0];
    const float* bw = (const float*)d_in[1];
    const float* sw = (const float*)d_in[2];
    // defensive: identify base (9 elems) vs spline (72 elems) weights by count
    if (n_in >= 3 && in_sizes[1] == 72 && in_sizes[2] == 9) {
        const float* t = bw; bw = sw; sw = t;
    }
    float* out = (float*)d_out;

    dim3 block(32, 4);
    dim3 grid((WO + 63) / 64,                 // 4 column strips
              (HO + 4 * RPW - 1) / (4 * RPW), // 8 row groups
              32);                            // batch
    kan_conv_kernel<<<grid, block>>>(x, bw, sw, out);
}